// round 13
// baseline (speedup 1.0000x reference)
#include <cuda_runtime.h>
#include <math.h>
#include <stdint.h>

#define BB 256
#define TT 1000
#define NN 200
#define NII 7
#define RR 4              // batch rows per cluster
#define YP 208            // padded y row (floats)

#define ALPHA_F 0.2f
#define OMA_F   0.8f
#define NSC_F   0.0948683292f   // 0.15*sqrt(2*0.2)

typedef unsigned long long u64;

__device__ __forceinline__ void ffma2(u64& acc, u64 w, u64 y) {
    asm("fma.rn.f32x2 %0, %1, %2, %0;" : "+l"(acc) : "l"(w), "l"(y));
}
__device__ __forceinline__ float hsum4(u64 a, u64 b) {
    u64 s; asm("add.rn.f32x2 %0, %1, %2;" : "=l"(s) : "l"(a), "l"(b));
    float2 f; asm("mov.b64 {%0, %1}, %2;" : "=f"(f.x), "=f"(f.y) : "l"(s));
    return f.x + f.y;
}
__device__ __forceinline__ uint32_t s2u(const void* p) {
    uint32_t a;
    asm("{ .reg .u64 t; cvta.to.shared.u64 t, %1; cvt.u32.u64 %0, t; }"
        : "=r"(a) : "l"(p));
    return a;
}
__device__ __forceinline__ uint32_t mapa_u32(uint32_t a, uint32_t r) {
    uint32_t o;
    asm("mapa.shared::cluster.u32 %0, %1, %2;" : "=r"(o) : "r"(a), "r"(r));
    return o;
}
__device__ __forceinline__ void st_cluster_f32(uint32_t addr, float v) {
    asm volatile("st.shared::cluster.f32 [%0], %1;" :: "r"(addr), "f"(v) : "memory");
}
__device__ __forceinline__ void mbar_arrive_remote(uint32_t addr) {
    asm volatile("mbarrier.arrive.release.cluster.shared::cluster.b64 _, [%0];"
                 :: "r"(addr) : "memory");
}
__device__ __forceinline__ void mbar_wait(uint32_t addr, uint32_t parity) {
    asm volatile("{\n\t.reg .pred P;\nWL%=:\n\t"
                 "mbarrier.try_wait.parity.acquire.cluster.shared::cta.b64 P, [%0], %1;\n\t"
                 "@P bra WD%=;\n\tbra WL%=;\nWD%=:\n}"
                 :: "r"(addr), "r"(parity) : "memory");
}

__global__ void __launch_bounds__(512, 1) __cluster_dims__(2, 1, 1)
rnn_nsplit_kernel(const float* __restrict__ y0,
                  const float* __restrict__ u_seq,
                  const float* __restrict__ noise,
                  const float* __restrict__ W_in_raw,
                  const float* __restrict__ W_rec,
                  const float* __restrict__ b_rec,
                  const float* __restrict__ w_out,
                  const float* __restrict__ b_out,
                  float* __restrict__ out)
{
    __shared__ __align__(16) float y_s[2][RR][YP];   // full y state, both halves
    __shared__ float u_s[2][RR][NII];
    __shared__ float wia_s[100 * 8];                 // |W_in| + b_rec for OWN neurons
    __shared__ __align__(8) u64 mbar[2];

    const int tid  = threadIdx.x;
    const int quad = tid >> 2;          // 0..127
    const int h    = tid & 3;           // K-quarter
    uint32_t rank; asm("mov.u32 %0, %%cluster_ctarank;" : "=r"(rank));
    const uint32_t peer = rank ^ 1u;
    const int rowbase = (int)(blockIdx.x >> 1) * RR;

    const bool is_dot  = (tid < 416);                  // warps 0..12, fully
    const bool is_neur = (quad < 100);
    const bool is_zq   = (quad == 100) && (rank == 1);
    const bool h0      = (h == 0);
    const int  n_glob  = 100 * (int)rank + quad;       // valid when is_neur
    const int  hoff    = h * 52 - ((h == 3) ? 4 : 0);  // {0,52,104,152}
    const int  wlen    = (h < 2) ? 26 : 24;            // real b64 count

    float* __restrict__ yseq = out;
    float* __restrict__ zseq = out + (size_t)BB * TT * NN;
    float* __restrict__ yfin = zseq + (size_t)BB * TT;

    // ---- mbarrier init: each CTA expects 100 remote arrivals per step ----
    if (tid == 0) {
        uint32_t m0 = s2u(&mbar[0]), m1 = s2u(&mbar[1]);
        asm volatile("mbarrier.init.shared.b64 [%0], %1;" :: "r"(m0), "r"(100u));
        asm volatile("mbarrier.init.shared.b64 [%0], %1;" :: "r"(m1), "r"(100u));
    }

    // ---- W quarter-chunk in registers (26 b64, zero tail for h>=2) ----
    u64 w[26];
    if (is_dot) {
        const float* row = is_neur ? (W_rec + (size_t)n_glob * NN) : w_out;
        const u64* wp = reinterpret_cast<const u64*>(row + hoff);
        #pragma unroll
        for (int m = 0; m < 26; ++m) w[m] = (m < wlen) ? __ldg(&wp[m]) : 0ull;
    }

    // ---- init smem: y0 (full 200), pads zeroed, wia, u[0] ----
    for (int i = tid; i < RR * YP; i += 512) {
        int r = i / YP, n = i % YP;
        float v = (n < NN) ? y0[(size_t)(rowbase + r) * NN + n] : 0.f;
        y_s[0][r][n] = v;
        y_s[1][r][n] = (n < NN) ? 0.f : 0.f;   // pads of buf1 = 0 too
    }
    for (int i = tid; i < 100 * 8; i += 512) {
        int n = i / 8, k = i % 8;
        wia_s[i] = (k < 7) ? fabsf(W_in_raw[(100 * rank + n) * NII + k])
                           : b_rec[100 * rank + n];
    }
    if (tid >= 448 && tid < 448 + RR * NII) {
        int q = tid - 448, r = q / NII, i = q % NII;
        u_s[0][r][i] = u_seq[(size_t)(rowbase + r) * TT * NII + i];
    }

    float bout = 0.f;
    if (is_zq) bout = b_out[0];

    float yv[RR], nz[RR];
    if (h0 && is_neur) {
        #pragma unroll
        for (int r = 0; r < RR; ++r) {
            yv[r] = y0[(size_t)(rowbase + r) * NN + n_glob];
            nz[r] = noise[(size_t)(rowbase + r) * TT * NN + n_glob];
        }
    }

    // ---- remote addresses ----
    const uint32_t rem_y[2] = { mapa_u32(s2u(&y_s[0][0][0]), peer),
                                mapa_u32(s2u(&y_s[1][0][0]), peer) };
    const uint32_t rem_mb[2] = { mapa_u32(s2u(&mbar[0]), peer),
                                 mapa_u32(s2u(&mbar[1]), peer) };
    const uint32_t my_mb[2]  = { s2u(&mbar[0]), s2u(&mbar[1]) };

    __syncthreads();
    asm volatile("barrier.cluster.arrive.aligned;" ::: "memory");
    asm volatile("barrier.cluster.wait.aligned;" ::: "memory");

    int buf = 0;
    for (int t = 0; t < TT; ++t) {
        const uint32_t ph = (uint32_t)((t >> 1) & 1);

        // prefetch noise[t+1] (epilogue lanes), u[t+1] (warp 14)
        float nzn[RR] = {0.f, 0.f, 0.f, 0.f};
        if (h0 && is_neur && (t + 1 < TT)) {
            #pragma unroll
            for (int r = 0; r < RR; ++r)
                nzn[r] = __ldcg(&noise[((size_t)(rowbase + r) * TT + (t + 1)) * NN + n_glob]);
        }
        float un = 0.f;
        if (tid >= 448 && tid < 448 + RR * NII && (t + 1 < TT)) {
            int q = tid - 448;
            un = __ldcg(&u_seq[((size_t)(rowbase + q / NII) * TT + (t + 1)) * NII + (q % NII)]);
        }

        if (is_dot) {
            // ---- quarter-dot: 4 rows, 8 chains, uniform 13 iterations ----
            const ulonglong2* Y0 = reinterpret_cast<const ulonglong2*>(&y_s[buf][0][hoff]);
            const ulonglong2* Y1 = reinterpret_cast<const ulonglong2*>(&y_s[buf][1][hoff]);
            const ulonglong2* Y2 = reinterpret_cast<const ulonglong2*>(&y_s[buf][2][hoff]);
            const ulonglong2* Y3 = reinterpret_cast<const ulonglong2*>(&y_s[buf][3][hoff]);
            u64 a0 = 0, b0 = 0, a1 = 0, b1 = 0, a2 = 0, b2 = 0, a3 = 0, b3 = 0;
            #pragma unroll
            for (int m = 0; m < 13; ++m) {
                ulonglong2 q0 = Y0[m], q1 = Y1[m], q2 = Y2[m], q3 = Y3[m];
                ffma2(a0, w[2 * m], q0.x); ffma2(b0, w[2 * m + 1], q0.y);
                ffma2(a1, w[2 * m], q1.x); ffma2(b1, w[2 * m + 1], q1.y);
                ffma2(a2, w[2 * m], q2.x); ffma2(b2, w[2 * m + 1], q2.y);
                ffma2(a3, w[2 * m], q3.x); ffma2(b3, w[2 * m + 1], q3.y);
            }
            float p0 = hsum4(a0, b0), p1 = hsum4(a1, b1);
            float p2 = hsum4(a2, b2), p3 = hsum4(a3, b3);
            // combine K-quarters within the lane quad
            p0 += __shfl_xor_sync(0xFFFFFFFFu, p0, 1);
            p0 += __shfl_xor_sync(0xFFFFFFFFu, p0, 2);
            p1 += __shfl_xor_sync(0xFFFFFFFFu, p1, 1);
            p1 += __shfl_xor_sync(0xFFFFFFFFu, p1, 2);
            p2 += __shfl_xor_sync(0xFFFFFFFFu, p2, 1);
            p2 += __shfl_xor_sync(0xFFFFFFFFu, p2, 2);
            p3 += __shfl_xor_sync(0xFFFFFFFFu, p3, 1);
            p3 += __shfl_xor_sync(0xFFFFFFFFu, p3, 2);

            if (h0 && is_neur) {
                float pr[RR] = {p0, p1, p2, p3};
                float4 wa = *reinterpret_cast<const float4*>(&wia_s[quad * 8]);
                float4 wb = *reinterpret_cast<const float4*>(&wia_s[quad * 8 + 4]);
                const int bufn = buf ^ 1;
                #pragma unroll
                for (int r = 0; r < RR; ++r) {
                    float dr = wb.w;                 // b_rec
                    dr = fmaf(wa.x, u_s[buf][r][0], dr);
                    dr = fmaf(wa.y, u_s[buf][r][1], dr);
                    dr = fmaf(wa.z, u_s[buf][r][2], dr);
                    dr = fmaf(wa.w, u_s[buf][r][3], dr);
                    dr = fmaf(wb.x, u_s[buf][r][4], dr);
                    dr = fmaf(wb.y, u_s[buf][r][5], dr);
                    dr = fmaf(wb.z, u_s[buf][r][6], dr);
                    float rl = fmaxf(pr[r] + dr, 0.f);
                    float yn = fmaf(OMA_F, yv[r], fmaf(ALPHA_F, rl, NSC_F * nz[r]));
                    y_s[bufn][r][n_glob] = yn;
                    st_cluster_f32(rem_y[bufn] + (uint32_t)(r * YP + n_glob) * 4u, yn);
                    __stcs(&yseq[((size_t)(rowbase + r) * TT + t) * NN + n_glob], yn);
                    yv[r] = yn;
                    nz[r] = nzn[r];
                }
                mbar_arrive_remote(rem_mb[buf]);
            } else if (h0 && is_zq && t >= 1) {
                // z dot was over S_t = yseq[t-1]
                zseq[(size_t)(rowbase + 0) * TT + (t - 1)] = 1.f / (1.f + expf(-(p0 + bout)));
                zseq[(size_t)(rowbase + 1) * TT + (t - 1)] = 1.f / (1.f + expf(-(p1 + bout)));
                zseq[(size_t)(rowbase + 2) * TT + (t - 1)] = 1.f / (1.f + expf(-(p2 + bout)));
                zseq[(size_t)(rowbase + 3) * TT + (t - 1)] = 1.f / (1.f + expf(-(p3 + bout)));
            }
        }
        if (tid >= 448 && tid < 448 + RR * NII && (t + 1 < TT)) {
            int q = tid - 448;
            u_s[buf ^ 1][q / NII][q % NII] = un;
        }
        mbar_wait(my_mb[buf], ph);     // peer's 100 y values for this step landed
        __syncthreads();               // own half + u visible
        buf ^= 1;
    }

    // ---- final z: dot over S_TT = y[T-1] (rank 1, warp 12 uniformly) ----
    if (rank == 1 && tid >= 384 && tid < 416) {
        const ulonglong2* Y0 = reinterpret_cast<const ulonglong2*>(&y_s[buf][0][hoff]);
        const ulonglong2* Y1 = reinterpret_cast<const ulonglong2*>(&y_s[buf][1][hoff]);
        const ulonglong2* Y2 = reinterpret_cast<const ulonglong2*>(&y_s[buf][2][hoff]);
        const ulonglong2* Y3 = reinterpret_cast<const ulonglong2*>(&y_s[buf][3][hoff]);
        u64 a0 = 0, b0 = 0, a1 = 0, b1 = 0, a2 = 0, b2 = 0, a3 = 0, b3 = 0;
        #pragma unroll
        for (int m = 0; m < 13; ++m) {
            ulonglong2 q0 = Y0[m], q1 = Y1[m], q2 = Y2[m], q3 = Y3[m];
            ffma2(a0, w[2 * m], q0.x); ffma2(b0, w[2 * m + 1], q0.y);
            ffma2(a1, w[2 * m], q1.x); ffma2(b1, w[2 * m + 1], q1.y);
            ffma2(a2, w[2 * m], q2.x); ffma2(b2, w[2 * m + 1], q2.y);
            ffma2(a3, w[2 * m], q3.x); ffma2(b3, w[2 * m + 1], q3.y);
        }
        float p0 = hsum4(a0, b0), p1 = hsum4(a1, b1);
        float p2 = hsum4(a2, b2), p3 = hsum4(a3, b3);
        p0 += __shfl_xor_sync(0xFFFFFFFFu, p0, 1);
        p0 += __shfl_xor_sync(0xFFFFFFFFu, p0, 2);
        p1 += __shfl_xor_sync(0xFFFFFFFFu, p1, 1);
        p1 += __shfl_xor_sync(0xFFFFFFFFu, p1, 2);
        p2 += __shfl_xor_sync(0xFFFFFFFFu, p2, 1);
        p2 += __shfl_xor_sync(0xFFFFFFFFu, p2, 2);
        p3 += __shfl_xor_sync(0xFFFFFFFFu, p3, 1);
        p3 += __shfl_xor_sync(0xFFFFFFFFu, p3, 2);
        if (tid == 400) {
            zseq[(size_t)(rowbase + 0) * TT + (TT - 1)] = 1.f / (1.f + expf(-(p0 + bout)));
            zseq[(size_t)(rowbase + 1) * TT + (TT - 1)] = 1.f / (1.f + expf(-(p1 + bout)));
            zseq[(size_t)(rowbase + 2) * TT + (TT - 1)] = 1.f / (1.f + expf(-(p2 + bout)));
            zseq[(size_t)(rowbase + 3) * TT + (TT - 1)] = 1.f / (1.f + expf(-(p3 + bout)));
        }
    }

    // ---- y_final ----
    if (h0 && is_neur) {
        #pragma unroll
        for (int r = 0; r < RR; ++r)
            yfin[(size_t)(rowbase + r) * NN + n_glob] = yv[r];
    }

    // ---- exit ordering: no CTA exits while peer remote ops may be in flight ----
    asm volatile("barrier.cluster.arrive.aligned;" ::: "memory");
    asm volatile("barrier.cluster.wait.aligned;" ::: "memory");
}

extern "C" void kernel_launch(void* const* d_in, const int* in_sizes, int n_in,
                              void* d_out, int out_size) {
    const float* y0       = (const float*)d_in[0];
    const float* u_seq    = (const float*)d_in[1];
    const float* noise    = (const float*)d_in[2];
    const float* W_in_raw = (const float*)d_in[3];
    const float* W_rec    = (const float*)d_in[4];
    const float* b_rec    = (const float*)d_in[5];
    const float* w_out    = (const float*)d_in[6];
    const float* b_out    = (const float*)d_in[7];
    float* out = (float*)d_out;

    rnn_nsplit_kernel<<<BB / 2, 512>>>(y0, u_seq, noise, W_in_raw, W_rec,
                                       b_rec, w_out, b_out, out);
}

// round 14
// speedup vs baseline: 1.9473x; 1.9473x over previous
#include <cuda_runtime.h>
#include <math.h>

// Problem constants
#define BB 256
#define TT 1000
#define NN 200
#define NII 7

#define ALPHA_F 0.2f
#define OMA_F   0.8f
#define NSC_F   0.0948683292f   // 0.15*sqrt(2*0.2)

typedef unsigned long long u64;

// 205MB scratch for the precomputed input drive (allowed: static __device__)
__device__ float g_drive[(size_t)BB * TT * NN];

__device__ __forceinline__ void ffma2(u64& acc, u64 w, u64 y) {
    asm("fma.rn.f32x2 %0, %1, %2, %0;" : "+l"(acc) : "l"(w), "l"(y));
}
__device__ __forceinline__ u64 add2(u64 a, u64 b) {
    u64 s; asm("add.rn.f32x2 %0, %1, %2;" : "=l"(s) : "l"(a), "l"(b));
    return s;
}
__device__ __forceinline__ float hsum8(u64 a, u64 b, u64 c, u64 d) {
    u64 s = add2(add2(a, b), add2(c, d));
    float2 f;
    asm("mov.b64 {%0, %1}, %2;" : "=f"(f.x), "=f"(f.y) : "l"(s));
    return f.x + f.y;
}

// ============ pre-kernel: drive = |W_in| . u + b_rec ============
__global__ void drive_kernel(const float* __restrict__ u_seq,
                             const float* __restrict__ W_in_raw,
                             const float* __restrict__ b_rec) {
    int t0 = blockIdx.x * 4;
    int b  = blockIdx.y;
    int n  = threadIdx.x;
    if (n >= NN) return;
    float wia[NII];
    #pragma unroll
    for (int i = 0; i < NII; ++i) wia[i] = fabsf(__ldg(&W_in_raw[n * NII + i]));
    float br = __ldg(&b_rec[n]);
    #pragma unroll
    for (int j = 0; j < 4; ++j) {
        int t = t0 + j;
        float d = br;
        #pragma unroll
        for (int i = 0; i < NII; ++i)
            d = fmaf(wia[i], __ldg(&u_seq[((size_t)b * TT + t) * NII + i]), d);
        g_drive[((size_t)b * TT + t) * NN + n] = d;
    }
}

// ============ main persistent recurrence kernel ============
__global__ void __launch_bounds__(256, 1)
rnn_main(const float* __restrict__ y0,
         const float* __restrict__ noise,
         const float* __restrict__ W_rec,
         float* __restrict__ out)
{
    __shared__ __align__(16) float y_s[2][2][NN];   // [buf][row][neuron]

    const int tid = threadIdx.x;
    const bool act = (tid < NN);
    const int  n   = act ? tid : 0;
    const int  b0  = blockIdx.x * 2;
    const int  b1  = b0 + 1;

    float* __restrict__ yseq = out;
    float* __restrict__ yfin = out + (size_t)BB * TT * NN + (size_t)BB * TT;

    // ---- full W row in registers (200 fp32 = 100 x b64) ----
    u64 w[NN / 2];
    if (act) {
        const u64* wp = reinterpret_cast<const u64*>(W_rec + (size_t)n * NN);
        #pragma unroll
        for (int m = 0; m < NN / 2; ++m) w[m] = __ldg(&wp[m]);
    }

    float yold0 = 0.f, yold1 = 0.f;
    float nz0 = 0.f, nz1 = 0.f, dr0 = 0.f, dr1 = 0.f;
    const float* np0 = noise   + (size_t)b0 * TT * NN + n;
    const float* np1 = noise   + (size_t)b1 * TT * NN + n;
    const float* dp0 = g_drive + (size_t)b0 * TT * NN + n;
    const float* dp1 = g_drive + (size_t)b1 * TT * NN + n;
    float* yp0 = yseq + (size_t)b0 * TT * NN + n;
    float* yp1 = yseq + (size_t)b1 * TT * NN + n;

    if (act) {
        yold0 = y0[(size_t)b0 * NN + n];
        yold1 = y0[(size_t)b1 * NN + n];
        y_s[0][0][n] = yold0;
        y_s[0][1][n] = yold1;
        nz0 = __ldcs(np0); nz1 = __ldcs(np1);
        dr0 = __ldcs(dp0); dr1 = __ldcs(dp1);
    }
    __syncthreads();

    int buf = 0;
    for (int t = 0; t < TT; ++t) {
        // prefetch next step's noise + drive (4 coalesced LDGs)
        float nz0n = 0.f, nz1n = 0.f, dr0n = 0.f, dr1n = 0.f;
        if (act && (t + 1 < TT)) {
            nz0n = __ldcs(np0 + (t + 1) * NN);
            nz1n = __ldcs(np1 + (t + 1) * NN);
            dr0n = __ldcs(dp0 + (t + 1) * NN);
            dr1n = __ldcs(dp1 + (t + 1) * NN);
        }

        if (act) {
            // ---- dot: 100 LDS.128, 200 FFMA2, 8 independent chains ----
            const ulonglong2* Y0 = reinterpret_cast<const ulonglong2*>(y_s[buf][0]);
            const ulonglong2* Y1 = reinterpret_cast<const ulonglong2*>(y_s[buf][1]);
            u64 c0a = 0, c0b = 0, c0c = 0, c0d = 0;
            u64 c1a = 0, c1b = 0, c1c = 0, c1d = 0;
            #pragma unroll
            for (int m = 0; m < NN / 8; ++m) {      // 25 iters x 8 floats/row
                ulonglong2 pA = Y0[2 * m], pB = Y0[2 * m + 1];
                ulonglong2 qA = Y1[2 * m], qB = Y1[2 * m + 1];
                ffma2(c0a, w[4 * m + 0], pA.x);
                ffma2(c0b, w[4 * m + 1], pA.y);
                ffma2(c1a, w[4 * m + 0], qA.x);
                ffma2(c1b, w[4 * m + 1], qA.y);
                ffma2(c0c, w[4 * m + 2], pB.x);
                ffma2(c0d, w[4 * m + 3], pB.y);
                ffma2(c1c, w[4 * m + 2], qB.x);
                ffma2(c1d, w[4 * m + 3], qB.y);
            }
            float pre0 = hsum8(c0a, c0b, c0c, c0d);
            float pre1 = hsum8(c1a, c1b, c1c, c1d);

            // ---- epilogue: y' = 0.8 y + 0.2 relu(pre + drive) + NSC*noise ----
            float r0 = fmaxf(pre0 + dr0, 0.f);
            float r1 = fmaxf(pre1 + dr1, 0.f);
            float yn0 = fmaf(OMA_F, yold0, fmaf(ALPHA_F, r0, NSC_F * nz0));
            float yn1 = fmaf(OMA_F, yold1, fmaf(ALPHA_F, r1, NSC_F * nz1));
            y_s[buf ^ 1][0][n] = yn0;
            y_s[buf ^ 1][1][n] = yn1;
            __stcs(yp0, yn0);
            __stcs(yp1, yn1);
            yp0 += NN; yp1 += NN;
            yold0 = yn0; yold1 = yn1;
            nz0 = nz0n; nz1 = nz1n;
            dr0 = dr0n; dr1 = dr1n;
        }
        __syncthreads();
        buf ^= 1;
    }

    if (act) {
        yfin[(size_t)b0 * NN + n] = yold0;
        yfin[(size_t)b1 * NN + n] = yold1;
    }
}

// ============ post-kernel: z = sigmoid(y_seq . w_out + b_out) ============
__global__ void z_kernel(const float* __restrict__ w_out,
                         const float* __restrict__ b_out,
                         float* __restrict__ out)
{
    __shared__ float wsm[NN];
    const int tid = threadIdx.x, lane = tid & 31, wid = tid >> 5;
    for (int i = tid; i < NN; i += 256) wsm[i] = w_out[i];
    __syncthreads();

    size_t idx = (size_t)blockIdx.x * 8 + wid;      // linear (b*TT + t)
    const float* y = out + idx * NN;
    float s = 0.f;
    #pragma unroll
    for (int k = lane; k < NN; k += 32)
        s = fmaf(__ldcs(&y[k]), wsm[k], s);
    s += __shfl_xor_sync(0xFFFFFFFFu, s, 16);
    s += __shfl_xor_sync(0xFFFFFFFFu, s, 8);
    s += __shfl_xor_sync(0xFFFFFFFFu, s, 4);
    s += __shfl_xor_sync(0xFFFFFFFFu, s, 2);
    s += __shfl_xor_sync(0xFFFFFFFFu, s, 1);
    if (lane == 0) {
        float* zseq = out + (size_t)BB * TT * NN;
        zseq[idx] = 1.f / (1.f + expf(-(s + b_out[0])));
    }
}

extern "C" void kernel_launch(void* const* d_in, const int* in_sizes, int n_in,
                              void* d_out, int out_size) {
    const float* y0       = (const float*)d_in[0];
    const float* u_seq    = (const float*)d_in[1];
    const float* noise    = (const float*)d_in[2];
    const float* W_in_raw = (const float*)d_in[3];
    const float* W_rec    = (const float*)d_in[4];
    const float* b_rec    = (const float*)d_in[5];
    const float* w_out    = (const float*)d_in[6];
    const float* b_out    = (const float*)d_in[7];
    float* out = (float*)d_out;

    dim3 dgrid(TT / 4, BB);
    drive_kernel<<<dgrid, 256>>>(u_seq, W_in_raw, b_rec);
    rnn_main<<<BB / 2, 256>>>(y0, noise, W_rec, out);
    z_kernel<<<(BB * TT) / 8, 256>>>(w_out, b_out, out);
}